// round 15
// baseline (speedup 1.0000x reference)
#include <cuda_runtime.h>
#include <math.h>
#include <stdint.h>

// B=4, S=4096, D=512, H=8, hd=64, SEG=256, Q=1 (fixed-shape problem)
#define B_   4
#define S_   4096
#define D_   512
#define H_   8
#define HD_  64
#define SEG_ 256
#define TCH  8     // tokens per k_main chunk (R8-proven)

// ---------------- device scratch (fully rewritten every launch) -----------------------
__device__ __align__(16) float g_C[H_ * D_];
__device__              int   g_start[B_ * (SEG_ + 1)];
__device__ __align__(16) float g_Z[B_ * H_ * SEG_];
__device__ __align__(16) float g_Zpart[B_ * H_ * 8];
__device__ __align__(16) float g_U[B_ * H_ * SEG_ * D_];     // 16.8 MB (tf32-rounded)
__device__ __align__(16) float g_A[B_ * SEG_ * D_];
__device__ __align__(16) float g_Apart[B_ * 8 * D_];
__device__ __align__(16) float g_wvr[D_ * D_];               // wv pre-rounded to tf32 (RNA)
__device__ __align__(16) float g_wor[D_ * D_];               // wo pre-rounded to tf32 (RNA)

// ---------------- tf32 mma helpers ----------------------------------------------------
__device__ __forceinline__ uint32_t f2tf32(float v) {
    uint32_t r;
    asm("cvt.rna.tf32.f32 %0, %1;" : "=r"(r) : "f"(v));
    return r;
}
__device__ __forceinline__ void mma_tf32(float c[4],
                                         uint32_t a0, uint32_t a1, uint32_t a2, uint32_t a3,
                                         uint32_t b0, uint32_t b1) {
    asm volatile("mma.sync.aligned.m16n8k8.row.col.f32.tf32.tf32.f32 "
                 "{%0,%1,%2,%3}, {%4,%5,%6,%7}, {%8,%9}, {%0,%1,%2,%3};"
                 : "+f"(c[0]), "+f"(c[1]), "+f"(c[2]), "+f"(c[3])
                 : "r"(a0), "r"(a1), "r"(a2), "r"(a3), "r"(b0), "r"(b1));
}
__device__ __forceinline__ uint32_t s2u(const void* p) {
    return (uint32_t)__cvta_generic_to_shared(p);
}
#define LDSM4(a0, a1, a2, a3, addr) \
    asm volatile("ldmatrix.sync.aligned.m8n8.x4.shared.b16 {%0,%1,%2,%3}, [%4];" \
                 : "=r"(a0), "=r"(a1), "=r"(a2), "=r"(a3) : "r"(addr))
#define LDSM2(b0, b1, addr) \
    asm volatile("ldmatrix.sync.aligned.m8n8.x2.shared.b16 {%0,%1}, [%2];" \
                 : "=r"(b0), "=r"(b1) : "r"(addr))
__device__ __forceinline__ void cpa16(void* dst, const void* src) {
    asm volatile("cp.async.ca.shared.global [%0], [%1], 16;"
                 :: "r"(s2u(dst)), "l"(src));
}
#define CP_COMMIT() asm volatile("cp.async.commit_group;")
#define CP_WAIT0()  asm volatile("cp.async.wait_group 0;")

// ---------------- k_pre: C (0..15), bounds (16..19), weight rounding (20..147) --------
__global__ __launch_bounds__(256) void k_pre(const float* __restrict__ qb,
                                             const float* __restrict__ wq,
                                             const float* __restrict__ wk,
                                             const float* __restrict__ wv,
                                             const float* __restrict__ wo,
                                             const int*   __restrict__ seg) {
    const int bid = blockIdx.x;
    const int tid = threadIdx.x;
    if (bid < 16) {
        const int h  = bid >> 1;
        const int jh = bid & 1;
        __shared__ __align__(16) float qbs[D_];
        __shared__ float q0s[HD_];
        qbs[tid]       = qb[tid];
        qbs[tid + 256] = qb[tid + 256];
        __syncthreads();
        const int w = tid >> 5, lane = tid & 31;
        const float4* qb4 = reinterpret_cast<const float4*>(qbs);
        const float4* wq4 = reinterpret_cast<const float4*>(wq);
#pragma unroll
        for (int i = 0; i < 8; i++) {
            const int d = w + 8 * i;
            float p = 0.f;
#pragma unroll
            for (int j = 0; j < 4; j++) {
                float4 a = wq4[(size_t)(h * HD_ + d) * 128 + lane + 32 * j];
                float4 b = qb4[lane + 32 * j];
                p = fmaf(a.x, b.x, fmaf(a.y, b.y, fmaf(a.z, b.z, fmaf(a.w, b.w, p))));
            }
#pragma unroll
            for (int o = 16; o; o >>= 1) p += __shfl_xor_sync(0xffffffffu, p, o);
            if (lane == 0) q0s[d] = p;
        }
        __syncthreads();
        const int j = jh * 256 + tid;
        float s = 0.f;
#pragma unroll 8
        for (int d = 0; d < HD_; ++d)
            s = fmaf(q0s[d], wk[(size_t)(h * HD_ + d) * D_ + j], s);
        g_C[h * D_ + j] = s * 0.125f;
    } else if (bid < 20) {
        const int b = bid - 16;
        const int* sb = seg + b * S_;
        for (int s = tid; s < S_; s += 256) {
            int cur = sb[s];
            int prev = sb[(s == 0) ? 0 : s - 1];
            if (s == 0) prev = -1;
            for (int g = prev + 1; g <= cur; ++g) g_start[b * (SEG_ + 1) + g] = s;
        }
        if (tid == 0) {
            int last = sb[S_ - 1];
            for (int g = last + 1; g <= SEG_; ++g) g_start[b * (SEG_ + 1) + g] = S_;
        }
    } else {
        // round wv (blocks 20..83) / wo (blocks 84..147) to tf32 RNA
        const int r = bid - 20;               // 0..127
        const float4* src = reinterpret_cast<const float4*>((r < 64) ? wv : wo);
        float4* dst = reinterpret_cast<float4*>((r < 64) ? g_wvr : g_wor);
        const int base = (r & 63) * 1024;     // 8 rows x 128 float4 per block
#pragma unroll
        for (int i = 0; i < 4; i++) {
            int idx = base + tid + i * 256;
            float4 v = src[idx];
            float4 o;
            o.x = __uint_as_float(f2tf32(v.x));
            o.y = __uint_as_float(f2tf32(v.y));
            o.z = __uint_as_float(f2tf32(v.z));
            o.w = __uint_as_float(f2tf32(v.w));
            dst[idx] = o;
        }
    }
}

// ---------------- k_main: per-(b,seg), 8-token chunks; U stored tf32-rounded ----------
__global__ __launch_bounds__(256) void k_main(const float* __restrict__ x) {
    const int seg = blockIdx.x, b = blockIdx.y;
    const int tid = threadIdx.x;
    const int w = tid >> 5, lane = tid & 31;
    __shared__ __align__(16) float xs[TCH][D_];
    __shared__ __align__(16) float es[TCH][H_];
    const int s0 = g_start[b * (SEG_ + 1) + seg];
    const int s1 = g_start[b * (SEG_ + 1) + seg + 1];

    const float4* C4 = reinterpret_cast<const float4*>(g_C);
    float4 cC[4];
#pragma unroll
    for (int j = 0; j < 4; j++) cC[j] = C4[w * 128 + lane + 32 * j];

    float acc[2 * H_];
#pragma unroll
    for (int i = 0; i < 2 * H_; i++) acc[i] = 0.f;
    float zsum = 0.f;

    const float4* x4 = reinterpret_cast<const float4*>(x);
    float4* xs4 = reinterpret_cast<float4*>(xs);
    const float2* xs2 = reinterpret_cast<const float2*>(xs);
    const float4* es4 = reinterpret_cast<const float4*>(es);

    for (int t0 = s0; t0 < s1; t0 += TCH) {
        __syncthreads();
#pragma unroll
        for (int i = 0; i < 4; i++) {
            int idx = tid + i * 256;
            int r = idx >> 7;
            int tt = t0 + r;
            int tcl = (tt < s1) ? tt : (s1 - 1);
            float4 v = x4[(size_t)(b * S_ + tcl) * 128 + (idx & 127)];
            if (tt >= s1) v = make_float4(0.f, 0.f, 0.f, 0.f);
            xs4[idx] = v;
        }
        __syncthreads();
        float p[TCH];
#pragma unroll
        for (int t = 0; t < TCH; t++) {
            float s = 0.f;
#pragma unroll
            for (int j = 0; j < 4; j++) {
                float4 xv = xs4[t * 128 + lane + 32 * j];
                s = fmaf(xv.x, cC[j].x, fmaf(xv.y, cC[j].y,
                    fmaf(xv.z, cC[j].z, fmaf(xv.w, cC[j].w, s))));
            }
            p[t] = s;
        }
#pragma unroll
        for (int t = 0; t < TCH; t++)
#pragma unroll
            for (int o = 16; o; o >>= 1) p[t] += __shfl_xor_sync(0xffffffffu, p[t], o);
        float pv = p[0];
#pragma unroll
        for (int t = 1; t < TCH; t++) if (lane == t) pv = p[t];
        float e = (lane < TCH && t0 + lane < s1) ? expf(pv) : 0.f;
        if (lane < TCH) es[lane][w] = e;
        float ez = e;
#pragma unroll
        for (int o = 16; o; o >>= 1) ez += __shfl_xor_sync(0xffffffffu, ez, o);
        zsum += ez;
        __syncthreads();
#pragma unroll
        for (int t = 0; t < TCH; t++) {
            float2 xv = xs2[t * 256 + tid];
            float4 ea = es4[t * 2];
            float4 eb = es4[t * 2 + 1];
            acc[0]  = fmaf(ea.x, xv.x, acc[0]);  acc[1]  = fmaf(ea.x, xv.y, acc[1]);
            acc[2]  = fmaf(ea.y, xv.x, acc[2]);  acc[3]  = fmaf(ea.y, xv.y, acc[3]);
            acc[4]  = fmaf(ea.z, xv.x, acc[4]);  acc[5]  = fmaf(ea.z, xv.y, acc[5]);
            acc[6]  = fmaf(ea.w, xv.x, acc[6]);  acc[7]  = fmaf(ea.w, xv.y, acc[7]);
            acc[8]  = fmaf(eb.x, xv.x, acc[8]);  acc[9]  = fmaf(eb.x, xv.y, acc[9]);
            acc[10] = fmaf(eb.y, xv.x, acc[10]); acc[11] = fmaf(eb.y, xv.y, acc[11]);
            acc[12] = fmaf(eb.z, xv.x, acc[12]); acc[13] = fmaf(eb.z, xv.y, acc[13]);
            acc[14] = fmaf(eb.w, xv.x, acc[14]); acc[15] = fmaf(eb.w, xv.y, acc[15]);
        }
    }
    // store U pre-rounded to tf32 (RNA) so k_proj's raw cp.async + mma truncation == RNA
#pragma unroll
    for (int h = 0; h < H_; h++) {
        float2 v;
        v.x = __uint_as_float(f2tf32(acc[2 * h]));
        v.y = __uint_as_float(f2tf32(acc[2 * h + 1]));
        *reinterpret_cast<float2*>(g_U + ((size_t)((b * H_ + h) * SEG_ + seg)) * D_ + 2 * tid) = v;
    }
    if (lane == 0) g_Z[(b * H_ + w) * SEG_ + seg] = zsum;
}

// ---------------- k_proj: A = U @ wv_h^T, full cp.async (A+B), ldmatrix, mma ----------
__global__ __launch_bounds__(256) void k_proj() {
    const int st = blockIdx.x;        // 0..7
    const int h  = blockIdx.y;
    const int b  = blockIdx.z;
    const int tid = threadIdx.x;
    const int wid = tid >> 5, lane = tid & 31;
    const int wm = wid & 1, wn = wid >> 1;
    __shared__ __align__(16) uint32_t As[2][32][36];
    __shared__ __align__(16) uint32_t Bs[2][64][36];
    __shared__ float Cs[32][65];
    __shared__ float zsh[32];

    const float4* U4  = reinterpret_cast<const float4*>(
        g_U + ((size_t)((b * H_ + h) * SEG_ + st * 32)) * D_);
    const float4* Wv4 = reinterpret_cast<const float4*>(g_wvr);

    // stage both operands raw via cp.async (values pre-rounded to tf32 upstream)
    auto issue = [&](int s) {
        cpa16(&As[s & 1][tid >> 3][(tid & 7) * 4],
              U4 + (size_t)(tid >> 3) * 128 + s * 8 + (tid & 7));
#pragma unroll
        for (int i = 0; i < 2; i++) {
            int idx = tid + i * 256;
            cpa16(&Bs[s & 1][idx >> 3][(idx & 7) * 4],
                  Wv4 + (size_t)(h * HD_ + (idx >> 3)) * 128 + s * 8 + (idx & 7));
        }
        CP_COMMIT();
    };
    issue(0);

    if (tid >= 64 && tid < 96)
        zsh[tid - 64] = g_Z[(b * H_ + h) * SEG_ + st * 32 + (tid - 64)];

    float c[2][4];
#pragma unroll
    for (int ni = 0; ni < 2; ni++)
#pragma unroll
        for (int k = 0; k < 4; k++) c[ni][k] = 0.f;

    // ldmatrix base addresses (loop-invariant; +k8*4B per step)
    const int rb = wm * 16;
    uint32_t aBase[2], bBase[2][2];
    {
        int arow = rb + (lane & 15);
        int acol = (lane >> 4) * 4;
#pragma unroll
        for (int s = 0; s < 2; s++) {
            aBase[s] = s2u(&As[s][arow][acol]);
#pragma unroll
            for (int ni = 0; ni < 2; ni++) {
                int brow = wn * 16 + ni * 8 + (lane & 7);
                int bcol = ((lane >> 3) & 1) * 4;
                bBase[s][ni] = s2u(&Bs[s][brow][bcol]);
            }
        }
    }

    for (int it = 0; it < 16; it++) {
        CP_WAIT0();
        __syncthreads();
        if (it < 15) issue(it + 1);              // writes buffers[1-bs]; overlaps mma
        const int bs = it & 1;
#pragma unroll
        for (int k8 = 0; k8 < 32; k8 += 8) {
            uint32_t a0, a1, a2, a3;
            LDSM4(a0, a1, a2, a3, aBase[bs] + k8 * 4);
#pragma unroll
            for (int ni = 0; ni < 2; ni++) {
                uint32_t b0, b1;
                LDSM2(b0, b1, bBase[bs][ni] + k8 * 4);
                mma_tf32(c[ni], a0, a1, a2, a3, b0, b1);
            }
        }
    }
    // epilogue: g_A + stage C tile for Apart/Zpart reductions
    const int g = lane >> 2, t = lane & 3;
    const int r0 = rb + g;
#pragma unroll
    for (int ni = 0; ni < 2; ni++) {
        int col = wn * 16 + ni * 8 + 2 * t;
        size_t rowA0 = (size_t)(b * SEG_ + st * 32 + r0) * D_ + h * HD_;
        *reinterpret_cast<float2*>(g_A + rowA0 + col) = make_float2(c[ni][0], c[ni][1]);
        *reinterpret_cast<float2*>(g_A + rowA0 + 8 * D_ + col) = make_float2(c[ni][2], c[ni][3]);
        Cs[r0][col]     = c[ni][0];  Cs[r0][col + 1]     = c[ni][1];
        Cs[r0 + 8][col] = c[ni][2];  Cs[r0 + 8][col + 1] = c[ni][3];
    }
    __syncthreads();
    if (tid < 64) {
        float s = 0.f;
#pragma unroll
        for (int r = 0; r < 32; r++) s += Cs[r][tid];
        g_Apart[(size_t)(b * 8 + st) * D_ + h * HD_ + tid] = s;
    }
    if (tid == 0) {
        float z = 0.f;
#pragma unroll
        for (int r = 0; r < 32; r++) z += zsh[r];
        g_Zpart[(b * H_ + h) * 8 + st] = z;
    }
}

// ---------------- k_out: y = [(Aall - A) * invz] @ wo^T, ldmatrix + cp.async B --------
__global__ __launch_bounds__(256) void k_out(float* __restrict__ y) {
    const int mt = blockIdx.x;        // 0..31
    const int nt = blockIdx.y;        // 0..7
    const int tid = threadIdx.x;
    const int wid = tid >> 5, lane = tid & 31;
    const int wm = wid & 1, wn = wid >> 1;
    __shared__ __align__(16) uint32_t As[2][32][36];
    __shared__ __align__(16) uint32_t Bs[2][64][36];
    __shared__ float invz[32][H_];
    __shared__ __align__(16) float aall[D_];
    __shared__ float zall[H_];
    const int row0 = mt * 32;
    const int b = row0 / SEG_;
    const int l0 = row0 - b * SEG_;

    const float4* wo4 = reinterpret_cast<const float4*>(g_wor);   // pre-rounded tf32

    auto issueB = [&](int s) {
#pragma unroll
        for (int i = 0; i < 2; i++) {
            int idx = tid + i * 256;
            cpa16(&Bs[s & 1][idx >> 3][(idx & 7) * 4],
                  wo4 + (size_t)(nt * 64 + (idx >> 3)) * 128 + s * 8 + (idx & 7));
        }
        CP_COMMIT();
    };
    issueB(0);   // overlap with prologue

    for (int k = tid; k < D_; k += 256) {
        float s = 0.f;
#pragma unroll
        for (int st = 0; st < 8; st++) s += g_Apart[(size_t)(b * 8 + st) * D_ + k];
        aall[k] = s;
    }
    if (tid < H_) {
        float z = 0.f;
#pragma unroll
        for (int st = 0; st < 8; st++) z += g_Zpart[(b * H_ + tid) * 8 + st];
        zall[tid] = z;
    }
    __syncthreads();
    if (tid < 32 * H_) {
        int r = tid >> 3, h = tid & 7;
        invz[r][h] = 1.f / (zall[h] - g_Z[(b * H_ + h) * SEG_ + l0 + r]);
    }
    __syncthreads();

    float c[2][4];
#pragma unroll
    for (int ni = 0; ni < 2; ni++)
#pragma unroll
        for (int k = 0; k < 4; k++) c[ni][k] = 0.f;

    const float4* A4  = reinterpret_cast<const float4*>(g_A);
    const float4* aa4 = reinterpret_cast<const float4*>(aall);

    // ldmatrix base addresses
    const int rb = wm * 16;
    uint32_t aBase[2], bBase[2][2];
    {
        int arow = rb + (lane & 15);
        int acol = (lane >> 4) * 4;
#pragma unroll
        for (int s = 0; s < 2; s++) {
            aBase[s] = s2u(&As[s][arow][acol]);
#pragma unroll
            for (int ni = 0; ni < 2; ni++) {
                int brow = wn * 16 + ni * 8 + (lane & 7);
                int bcol = ((lane >> 3) & 1) * 4;
                bBase[s][ni] = s2u(&Bs[s][brow][bcol]);
            }
        }
    }

    const int ra = tid >> 3, ca = tid & 7;
    float4 pa;
    pa = A4[(size_t)(row0 + ra) * 128 + ca];
    {
        float4 al = aa4[ca];
        float iz = invz[ra][0];
        *reinterpret_cast<uint4*>(&As[0][ra][ca * 4]) =
            make_uint4(f2tf32((al.x - pa.x) * iz), f2tf32((al.y - pa.y) * iz),
                       f2tf32((al.z - pa.z) * iz), f2tf32((al.w - pa.w) * iz));
    }

    for (int it = 0; it < 16; it++) {
        CP_WAIT0();
        __syncthreads();
        if (it < 15) {
            issueB(it + 1);
            pa = A4[(size_t)(row0 + ra) * 128 + (it + 1) * 8 + ca];
        }
        const int bs = it & 1;
#pragma unroll
        for (int k8 = 0; k8 < 32; k8 += 8) {
            uint32_t a0, a1, a2, a3;
            LDSM4(a0, a1, a2, a3, aBase[bs] + k8 * 4);
#pragma unroll
            for (int ni = 0; ni < 2; ni++) {
                uint32_t b0, b1;
                LDSM2(b0, b1, bBase[bs][ni] + k8 * 4);
                mma_tf32(c[ni], a0, a1, a2, a3, b0, b1);
            }
        }
        if (it < 15) {
            const int ht = (it + 1) >> 1;    // head of next k-tile (32 k = half head)
            float4 al = aa4[(it + 1) * 8 + ca];
            float iz = invz[ra][ht];
            *reinterpret_cast<uint4*>(&As[1 - bs][ra][ca * 4]) =
                make_uint4(f2tf32((al.x - pa.x) * iz), f2tf32((al.y - pa.y) * iz),
                           f2tf32((al.z - pa.z) * iz), f2tf32((al.w - pa.w) * iz));
        }
    }
    {
        const int g = lane >> 2, t = lane & 3;
#pragma unroll
        for (int ni = 0; ni < 2; ni++) {
            int row = row0 + rb + g;
            int col = nt * 64 + wn * 16 + ni * 8 + 2 * t;
            *reinterpret_cast<float2*>(y + (size_t)row * D_ + col) = make_float2(c[ni][0], c[ni][1]);
            *reinterpret_cast<float2*>(y + (size_t)(row + 8) * D_ + col) = make_float2(c[ni][2], c[ni][3]);
        }
    }
}

// ---------------- launch ---------------------------------------------------------------
extern "C" void kernel_launch(void* const* d_in, const int* in_sizes, int n_in,
                              void* d_out, int out_size) {
    // order: x, seg_id, valid_mask, s_seg_max, query_bank, w_q, w_k, w_v, w_o
    const float* x   = (const float*)d_in[0];
    const int*   seg = (const int*)  d_in[1];
    const float* qb  = (const float*)d_in[4];
    const float* wq  = (const float*)d_in[5];
    const float* wk  = (const float*)d_in[6];
    const float* wv  = (const float*)d_in[7];
    const float* wo  = (const float*)d_in[8];
    float* y = (float*)d_out;

    k_pre <<<148, 256>>>(qb, wq, wk, wv, wo, seg);
    k_main<<<dim3(SEG_, B_), 256>>>(x);
    k_proj<<<dim3(SEG_ / 32, H_, B_), 256>>>();
    k_out <<<dim3(B_ * SEG_ / 32, D_ / 64), 256>>>(y);
}

// round 16
// speedup vs baseline: 1.0462x; 1.0462x over previous
#include <cuda_runtime.h>
#include <math.h>
#include <stdint.h>

// B=4, S=4096, D=512, H=8, hd=64, SEG=256, Q=1 (fixed-shape problem)
#define B_   4
#define S_   4096
#define D_   512
#define H_   8
#define HD_  64
#define SEG_ 256
#define TCH  8     // tokens per k_main chunk

// ---------------- device scratch (fully rewritten every launch) -----------------------
__device__ __align__(16) float g_C[H_ * D_];
__device__              int   g_start[B_ * (SEG_ + 1)];
__device__ __align__(16) float g_Z[B_ * H_ * SEG_];
__device__ __align__(16) float g_Zpart[B_ * H_ * 8];
__device__ __align__(16) float g_U[B_ * H_ * SEG_ * D_];     // 16.8 MB (tf32-rounded)
__device__ __align__(16) float g_A[B_ * SEG_ * D_];
__device__ __align__(16) float g_Apart[B_ * 8 * D_];
__device__ __align__(16) float g_wvr[D_ * D_];               // wv pre-rounded to tf32 (RNA)
__device__ __align__(16) float g_wor[D_ * D_];               // wo pre-rounded to tf32 (RNA)

// ---------------- tf32 mma helpers ----------------------------------------------------
__device__ __forceinline__ uint32_t f2tf32(float v) {
    uint32_t r;
    asm("cvt.rna.tf32.f32 %0, %1;" : "=r"(r) : "f"(v));
    return r;
}
__device__ __forceinline__ void mma_tf32(float c[4],
                                         uint32_t a0, uint32_t a1, uint32_t a2, uint32_t a3,
                                         uint32_t b0, uint32_t b1) {
    asm volatile("mma.sync.aligned.m16n8k8.row.col.f32.tf32.tf32.f32 "
                 "{%0,%1,%2,%3}, {%4,%5,%6,%7}, {%8,%9}, {%0,%1,%2,%3};"
                 : "+f"(c[0]), "+f"(c[1]), "+f"(c[2]), "+f"(c[3])
                 : "r"(a0), "r"(a1), "r"(a2), "r"(a3), "r"(b0), "r"(b1));
}
__device__ __forceinline__ uint32_t s2u(const void* p) {
    return (uint32_t)__cvta_generic_to_shared(p);
}
#define LDSM4(a0, a1, a2, a3, addr) \
    asm volatile("ldmatrix.sync.aligned.m8n8.x4.shared.b16 {%0,%1,%2,%3}, [%4];" \
                 : "=r"(a0), "=r"(a1), "=r"(a2), "=r"(a3) : "r"(addr))
#define LDSM2(b0, b1, addr) \
    asm volatile("ldmatrix.sync.aligned.m8n8.x2.shared.b16 {%0,%1}, [%2];" \
                 : "=r"(b0), "=r"(b1) : "r"(addr))
__device__ __forceinline__ void cpa16(void* dst, const void* src) {
    asm volatile("cp.async.ca.shared.global [%0], [%1], 16;"
                 :: "r"(s2u(dst)), "l"(src));
}
__device__ __forceinline__ void cpa16z(void* dst, const void* src, int sz) {
    // copies sz bytes (0 or 16) and zero-fills the remainder of the 16B
    asm volatile("cp.async.ca.shared.global [%0], [%1], 16, %2;"
                 :: "r"(s2u(dst)), "l"(src), "r"(sz));
}
#define CP_COMMIT() asm volatile("cp.async.commit_group;")
#define CP_WAIT0()  asm volatile("cp.async.wait_group 0;")

// ---------------- k_pre: C (0..15), bounds (16..19), weight rounding (20..147) --------
__global__ __launch_bounds__(256) void k_pre(const float* __restrict__ qb,
                                             const float* __restrict__ wq,
                                             const float* __restrict__ wk,
                                             const float* __restrict__ wv,
                                             const float* __restrict__ wo,
                                             const int*   __restrict__ seg) {
    const int bid = blockIdx.x;
    const int tid = threadIdx.x;
    if (bid < 16) {
        const int h  = bid >> 1;
        const int jh = bid & 1;
        __shared__ __align__(16) float qbs[D_];
        __shared__ float q0s[HD_];
        qbs[tid]       = qb[tid];
        qbs[tid + 256] = qb[tid + 256];
        __syncthreads();
        const int w = tid >> 5, lane = tid & 31;
        const float4* qb4 = reinterpret_cast<const float4*>(qbs);
        const float4* wq4 = reinterpret_cast<const float4*>(wq);
#pragma unroll
        for (int i = 0; i < 8; i++) {
            const int d = w + 8 * i;
            float p = 0.f;
#pragma unroll
            for (int j = 0; j < 4; j++) {
                float4 a = wq4[(size_t)(h * HD_ + d) * 128 + lane + 32 * j];
                float4 b = qb4[lane + 32 * j];
                p = fmaf(a.x, b.x, fmaf(a.y, b.y, fmaf(a.z, b.z, fmaf(a.w, b.w, p))));
            }
#pragma unroll
            for (int o = 16; o; o >>= 1) p += __shfl_xor_sync(0xffffffffu, p, o);
            if (lane == 0) q0s[d] = p;
        }
        __syncthreads();
        const int j = jh * 256 + tid;
        float s = 0.f;
#pragma unroll 8
        for (int d = 0; d < HD_; ++d)
            s = fmaf(q0s[d], wk[(size_t)(h * HD_ + d) * D_ + j], s);
        g_C[h * D_ + j] = s * 0.125f;
    } else if (bid < 20) {
        const int b = bid - 16;
        const int* sb = seg + b * S_;
        for (int s = tid; s < S_; s += 256) {
            int cur = sb[s];
            int prev = sb[(s == 0) ? 0 : s - 1];
            if (s == 0) prev = -1;
            for (int g = prev + 1; g <= cur; ++g) g_start[b * (SEG_ + 1) + g] = s;
        }
        if (tid == 0) {
            int last = sb[S_ - 1];
            for (int g = last + 1; g <= SEG_; ++g) g_start[b * (SEG_ + 1) + g] = S_;
        }
    } else {
        // round wv (blocks 20..83) / wo (blocks 84..147) to tf32 RNA
        const int r = bid - 20;               // 0..127
        const float4* src = reinterpret_cast<const float4*>((r < 64) ? wv : wo);
        float4* dst = reinterpret_cast<float4*>((r < 64) ? g_wvr : g_wor);
        const int base = (r & 63) * 1024;     // 8 rows x 128 float4 per block
#pragma unroll
        for (int i = 0; i < 4; i++) {
            int idx = base + tid + i * 256;
            float4 v = src[idx];
            float4 o;
            o.x = __uint_as_float(f2tf32(v.x));
            o.y = __uint_as_float(f2tf32(v.y));
            o.z = __uint_as_float(f2tf32(v.z));
            o.w = __uint_as_float(f2tf32(v.w));
            dst[idx] = o;
        }
    }
}

// ---------------- k_main: per-(b,seg), cp.async double-buffered 8-token chunks --------
__global__ __launch_bounds__(256) void k_main(const float* __restrict__ x) {
    const int seg = blockIdx.x, b = blockIdx.y;
    const int tid = threadIdx.x;
    const int w = tid >> 5, lane = tid & 31;
    __shared__ __align__(16) float xs[2][TCH][D_];   // 32 KB double buffer
    __shared__ __align__(16) float es[TCH][H_];
    const int s0 = g_start[b * (SEG_ + 1) + seg];
    const int s1 = g_start[b * (SEG_ + 1) + seg + 1];

    const float4* C4 = reinterpret_cast<const float4*>(g_C);
    float4 cC[4];
#pragma unroll
    for (int j = 0; j < 4; j++) cC[j] = C4[w * 128 + lane + 32 * j];

    float acc[2 * H_];
#pragma unroll
    for (int i = 0; i < 2 * H_; i++) acc[i] = 0.f;
    float zsum = 0.f;

    const float4* x4 = reinterpret_cast<const float4*>(x);
    const float4* es4 = reinterpret_cast<const float4*>(es);

    // issue one chunk's copies into buffer buf (zero-fill past segment end)
    auto issueX = [&](int t0, int buf) {
#pragma unroll
        for (int i = 0; i < 4; i++) {
            int idx = tid + i * 256;
            int r = idx >> 7;
            int tt = t0 + r;
            int tcl = (tt < s1) ? tt : (s1 - 1);   // in-bounds (only called when s0<s1)
            cpa16z(&xs[buf][0][0] + idx * 4,
                   x4 + (size_t)(b * S_ + tcl) * 128 + (idx & 127),
                   (tt < s1) ? 16 : 0);
        }
        CP_COMMIT();
    };

    const int nch = (s1 - s0 + TCH - 1) / TCH;     // 0 for empty segments
    if (nch > 0) issueX(s0, 0);

    for (int ci = 0; ci < nch; ci++) {
        const int t0 = s0 + ci * TCH;
        const int bs = ci & 1;
        CP_WAIT0();
        __syncthreads();                            // xs[bs] ready; prev es reads done
        if (ci + 1 < nch) issueX(t0 + TCH, 1 - bs); // overlaps with compute below
        const float4* xb4 = reinterpret_cast<const float4*>(xs[bs]);
        const float2* xb2 = reinterpret_cast<const float2*>(xs[bs]);
        // scores: warp w = head w, 8 tokens at once
        float p[TCH];
#pragma unroll
        for (int t = 0; t < TCH; t++) {
            float s = 0.f;
#pragma unroll
            for (int j = 0; j < 4; j++) {
                float4 xv = xb4[t * 128 + lane + 32 * j];
                s = fmaf(xv.x, cC[j].x, fmaf(xv.y, cC[j].y,
                    fmaf(xv.z, cC[j].z, fmaf(xv.w, cC[j].w, s))));
            }
            p[t] = s;
        }
#pragma unroll
        for (int t = 0; t < TCH; t++)
#pragma unroll
            for (int o = 16; o; o >>= 1) p[t] += __shfl_xor_sync(0xffffffffu, p[t], o);
        float pv = p[0];
#pragma unroll
        for (int t = 1; t < TCH; t++) if (lane == t) pv = p[t];
        float e = (lane < TCH && t0 + lane < s1) ? expf(pv) : 0.f;
        if (lane < TCH) es[lane][w] = e;
        float ez = e;
#pragma unroll
        for (int o = 16; o; o >>= 1) ez += __shfl_xor_sync(0xffffffffu, ez, o);
        zsum += ez;
        __syncthreads();                            // es ready
        // accumulate E_h * x into register-resident per-segment sums
#pragma unroll
        for (int t = 0; t < TCH; t++) {
            float2 xv = xb2[t * 256 + tid];
            float4 ea = es4[t * 2];
            float4 eb = es4[t * 2 + 1];
            acc[0]  = fmaf(ea.x, xv.x, acc[0]);  acc[1]  = fmaf(ea.x, xv.y, acc[1]);
            acc[2]  = fmaf(ea.y, xv.x, acc[2]);  acc[3]  = fmaf(ea.y, xv.y, acc[3]);
            acc[4]  = fmaf(ea.z, xv.x, acc[4]);  acc[5]  = fmaf(ea.z, xv.y, acc[5]);
            acc[6]  = fmaf(ea.w, xv.x, acc[6]);  acc[7]  = fmaf(ea.w, xv.y, acc[7]);
            acc[8]  = fmaf(eb.x, xv.x, acc[8]);  acc[9]  = fmaf(eb.x, xv.y, acc[9]);
            acc[10] = fmaf(eb.y, xv.x, acc[10]); acc[11] = fmaf(eb.y, xv.y, acc[11]);
            acc[12] = fmaf(eb.z, xv.x, acc[12]); acc[13] = fmaf(eb.z, xv.y, acc[13]);
            acc[14] = fmaf(eb.w, xv.x, acc[14]); acc[15] = fmaf(eb.w, xv.y, acc[15]);
        }
    }
    // store U pre-rounded to tf32 (RNA) so k_proj's raw cp.async + mma truncation == RNA
#pragma unroll
    for (int h = 0; h < H_; h++) {
        float2 v;
        v.x = __uint_as_float(f2tf32(acc[2 * h]));
        v.y = __uint_as_float(f2tf32(acc[2 * h + 1]));
        *reinterpret_cast<float2*>(g_U + ((size_t)((b * H_ + h) * SEG_ + seg)) * D_ + 2 * tid) = v;
    }
    if (lane == 0) g_Z[(b * H_ + w) * SEG_ + seg] = zsum;
}

// ---------------- k_proj: A = U @ wv_h^T, full cp.async (A+B), ldmatrix, mma ----------
__global__ __launch_bounds__(256) void k_proj() {
    const int st = blockIdx.x;        // 0..7
    const int h  = blockIdx.y;
    const int b  = blockIdx.z;
    const int tid = threadIdx.x;
    const int wid = tid >> 5, lane = tid & 31;
    const int wm = wid & 1, wn = wid >> 1;
    __shared__ __align__(16) uint32_t As[2][32][36];
    __shared__ __align__(16) uint32_t Bs[2][64][36];
    __shared__ float Cs[32][65];
    __shared__ float zsh[32];

    const float4* U4  = reinterpret_cast<const float4*>(
        g_U + ((size_t)((b * H_ + h) * SEG_ + st * 32)) * D_);
    const float4* Wv4 = reinterpret_cast<const float4*>(g_wvr);

    auto issue = [&](int s) {
        cpa16(&As[s & 1][tid >> 3][(tid & 7) * 4],
              U4 + (size_t)(tid >> 3) * 128 + s * 8 + (tid & 7));
#pragma unroll
        for (int i = 0; i < 2; i++) {
            int idx = tid + i * 256;
            cpa16(&Bs[s & 1][idx >> 3][(idx & 7) * 4],
                  Wv4 + (size_t)(h * HD_ + (idx >> 3)) * 128 + s * 8 + (idx & 7));
        }
        CP_COMMIT();
    };
    issue(0);

    if (tid >= 64 && tid < 96)
        zsh[tid - 64] = g_Z[(b * H_ + h) * SEG_ + st * 32 + (tid - 64)];

    float c[2][4];
#pragma unroll
    for (int ni = 0; ni < 2; ni++)
#pragma unroll
        for (int k = 0; k < 4; k++) c[ni][k] = 0.f;

    const int rb = wm * 16;
    uint32_t aBase[2], bBase[2][2];
    {
        int arow = rb + (lane & 15);
        int acol = (lane >> 4) * 4;
#pragma unroll
        for (int s = 0; s < 2; s++) {
            aBase[s] = s2u(&As[s][arow][acol]);
#pragma unroll
            for (int ni = 0; ni < 2; ni++) {
                int brow = wn * 16 + ni * 8 + (lane & 7);
                int bcol = ((lane >> 3) & 1) * 4;
                bBase[s][ni] = s2u(&Bs[s][brow][bcol]);
            }
        }
    }

    for (int it = 0; it < 16; it++) {
        CP_WAIT0();
        __syncthreads();
        if (it < 15) issue(it + 1);
        const int bs = it & 1;
#pragma unroll
        for (int k8 = 0; k8 < 32; k8 += 8) {
            uint32_t a0, a1, a2, a3;
            LDSM4(a0, a1, a2, a3, aBase[bs] + k8 * 4);
#pragma unroll
            for (int ni = 0; ni < 2; ni++) {
                uint32_t b0, b1;
                LDSM2(b0, b1, bBase[bs][ni] + k8 * 4);
                mma_tf32(c[ni], a0, a1, a2, a3, b0, b1);
            }
        }
    }
    const int g = lane >> 2, t = lane & 3;
    const int r0 = rb + g;
#pragma unroll
    for (int ni = 0; ni < 2; ni++) {
        int col = wn * 16 + ni * 8 + 2 * t;
        size_t rowA0 = (size_t)(b * SEG_ + st * 32 + r0) * D_ + h * HD_;
        *reinterpret_cast<float2*>(g_A + rowA0 + col) = make_float2(c[ni][0], c[ni][1]);
        *reinterpret_cast<float2*>(g_A + rowA0 + 8 * D_ + col) = make_float2(c[ni][2], c[ni][3]);
        Cs[r0][col]     = c[ni][0];  Cs[r0][col + 1]     = c[ni][1];
        Cs[r0 + 8][col] = c[ni][2];  Cs[r0 + 8][col + 1] = c[ni][3];
    }
    __syncthreads();
    if (tid < 64) {
        float s = 0.f;
#pragma unroll
        for (int r = 0; r < 32; r++) s += Cs[r][tid];
        g_Apart[(size_t)(b * 8 + st) * D_ + h * HD_ + tid] = s;
    }
    if (tid == 0) {
        float z = 0.f;
#pragma unroll
        for (int r = 0; r < 32; r++) z += zsh[r];
        g_Zpart[(b * H_ + h) * 8 + st] = z;
    }
}

// ---------------- k_out: y = [(Aall - A) * invz] @ wo^T, ldmatrix + cp.async B --------
__global__ __launch_bounds__(256) void k_out(float* __restrict__ y) {
    const int mt = blockIdx.x;        // 0..31
    const int nt = blockIdx.y;        // 0..7
    const int tid = threadIdx.x;
    const int wid = tid >> 5, lane = tid & 31;
    const int wm = wid & 1, wn = wid >> 1;
    __shared__ __align__(16) uint32_t As[2][32][36];
    __shared__ __align__(16) uint32_t Bs[2][64][36];
    __shared__ float invz[32][H_];
    __shared__ __align__(16) float aall[D_];
    __shared__ float zall[H_];
    const int row0 = mt * 32;
    const int b = row0 / SEG_;
    const int l0 = row0 - b * SEG_;

    const float4* wo4 = reinterpret_cast<const float4*>(g_wor);   // pre-rounded tf32

    auto issueB = [&](int s) {
#pragma unroll
        for (int i = 0; i < 2; i++) {
            int idx = tid + i * 256;
            cpa16(&Bs[s & 1][idx >> 3][(idx & 7) * 4],
                  wo4 + (size_t)(nt * 64 + (idx >> 3)) * 128 + s * 8 + (idx & 7));
        }
        CP_COMMIT();
    };
    issueB(0);   // overlap with prologue

    for (int k = tid; k < D_; k += 256) {
        float s = 0.f;
#pragma unroll
        for (int st = 0; st < 8; st++) s += g_Apart[(size_t)(b * 8 + st) * D_ + k];
        aall[k] = s;
    }
    if (tid < H_) {
        float z = 0.f;
#pragma unroll
        for (int st = 0; st < 8; st++) z += g_Zpart[(b * H_ + tid) * 8 + st];
        zall[tid] = z;
    }
    __syncthreads();
    if (tid < 32 * H_) {
        int r = tid >> 3, h = tid & 7;
        invz[r][h] = 1.f / (zall[h] - g_Z[(b * H_ + h) * SEG_ + l0 + r]);
    }
    __syncthreads();

    float c[2][4];
#pragma unroll
    for (int ni = 0; ni < 2; ni++)
#pragma unroll
        for (int k = 0; k < 4; k++) c[ni][k] = 0.f;

    const float4* A4  = reinterpret_cast<const float4*>(g_A);
    const float4* aa4 = reinterpret_cast<const float4*>(aall);

    const int rb = wm * 16;
    uint32_t aBase[2], bBase[2][2];
    {
        int arow = rb + (lane & 15);
        int acol = (lane >> 4) * 4;
#pragma unroll
        for (int s = 0; s < 2; s++) {
            aBase[s] = s2u(&As[s][arow][acol]);
#pragma unroll
            for (int ni = 0; ni < 2; ni++) {
                int brow = wn * 16 + ni * 8 + (lane & 7);
                int bcol = ((lane >> 3) & 1) * 4;
                bBase[s][ni] = s2u(&Bs[s][brow][bcol]);
            }
        }
    }

    const int ra = tid >> 3, ca = tid & 7;
    float4 pa;
    pa = A4[(size_t)(row0 + ra) * 128 + ca];
    {
        float4 al = aa4[ca];
        float iz = invz[ra][0];
        *reinterpret_cast<uint4*>(&As[0][ra][ca * 4]) =
            make_uint4(f2tf32((al.x - pa.x) * iz), f2tf32((al.y - pa.y) * iz),
                       f2tf32((al.z - pa.z) * iz), f2tf32((al.w - pa.w) * iz));
    }

    for (int it = 0; it < 16; it++) {
        CP_WAIT0();
        __syncthreads();
        if (it < 15) {
            issueB(it + 1);
            pa = A4[(size_t)(row0 + ra) * 128 + (it + 1) * 8 + ca];
        }
        const int bs = it & 1;
#pragma unroll
        for (int k8 = 0; k8 < 32; k8 += 8) {
            uint32_t a0, a1, a2, a3;
            LDSM4(a0, a1, a2, a3, aBase[bs] + k8 * 4);
#pragma unroll
            for (int ni = 0; ni < 2; ni++) {
                uint32_t b0, b1;
                LDSM2(b0, b1, bBase[bs][ni] + k8 * 4);
                mma_tf32(c[ni], a0, a1, a2, a3, b0, b1);
            }
        }
        if (it < 15) {
            const int ht = (it + 1) >> 1;    // head of next k-tile (32 k = half head)
            float4 al = aa4[(it + 1) * 8 + ca];
            float iz = invz[ra][ht];
            *reinterpret_cast<uint4*>(&As[1 - bs][ra][ca * 4]) =
                make_uint4(f2tf32((al.x - pa.x) * iz), f2tf32((al.y - pa.y) * iz),
                           f2tf32((al.z - pa.z) * iz), f2tf32((al.w - pa.w) * iz));
        }
    }
    {
        const int g = lane >> 2, t = lane & 3;
#pragma unroll
        for (int ni = 0; ni < 2; ni++) {
            int row = row0 + rb + g;
            int col = nt * 64 + wn * 16 + ni * 8 + 2 * t;
            *reinterpret_cast<float2*>(y + (size_t)row * D_ + col) = make_float2(c[ni][0], c[ni][1]);
            *reinterpret_cast<float2*>(y + (size_t)(row + 8) * D_ + col) = make_float2(c[ni][2], c[ni][3]);
        }
    }
}

// ---------------- launch ---------------------------------------------------------------
extern "C" void kernel_launch(void* const* d_in, const int* in_sizes, int n_in,
                              void* d_out, int out_size) {
    // order: x, seg_id, valid_mask, s_seg_max, query_bank, w_q, w_k, w_v, w_o
    const float* x   = (const float*)d_in[0];
    const int*   seg = (const int*)  d_in[1];
    const float* qb  = (const float*)d_in[4];
    const float* wq  = (const float*)d_in[5];
    const float* wk  = (const float*)d_in[6];
    const float* wv  = (const float*)d_in[7];
    const float* wo  = (const float*)d_in[8];
    float* y = (float*)d_out;

    k_pre <<<148, 256>>>(qb, wq, wk, wv, wo, seg);
    k_main<<<dim3(SEG_, B_), 256>>>(x);
    k_proj<<<dim3(SEG_ / 32, H_, B_), 256>>>();
    k_out <<<dim3(B_ * SEG_ / 32, D_ / 64), 256>>>(y);
}